// round 13
// baseline (speedup 1.0000x reference)
#include <cuda_runtime.h>
#include <math.h>

#define NH   64
#define NINP 128
#define NHID 512
#define NOUT 256
#define NSM  4
#define TINYF 1e-14f

// ---------------- scratch (device globals; no allocations allowed) ----------
__device__ float g_sub[NH * NINP];            // x @ qw_h per head
__device__ float g_h1pre[NH * NHID];          // w1 @ sub, pre-GN
__device__ float g_h1[NH * NHID];             // softplus(GN1(h1pre))
__device__ float g_z[NSM * NH * NOUT];        // w2 @ h1, pre-GN2, [s][h][o]
__device__ float g_partial[NSM * NH * NOUT];  // softmax per (s,h), [s][h][o]
__device__ float g_scalar_ho[NH * NOUT];      // ws row sums, [h][o]
__device__ float g_lp[NOUT];                  // prod over heads of last_out_sm

// ---------------- reduction helpers -----------------------------------------
__device__ __forceinline__ float warpSum(float v) {
#pragma unroll
    for (int o = 16; o; o >>= 1) v += __shfl_xor_sync(0xffffffffu, v, o);
    return v;
}
__device__ __forceinline__ float warpMax(float v) {
#pragma unroll
    for (int o = 16; o; o >>= 1) v = fmaxf(v, __shfl_xor_sync(0xffffffffu, v, o));
    return v;
}
__device__ __forceinline__ float warpProd(float v) {
#pragma unroll
    for (int o = 16; o; o >>= 1) v *= __shfl_xor_sync(0xffffffffu, v, o);
    return v;
}
template <int NW>
__device__ __forceinline__ float blockSum(float v, float* red) {
    int w = threadIdx.x >> 5, lane = threadIdx.x & 31;
    v = warpSum(v);
    __syncthreads();
    if (lane == 0) red[w] = v;
    __syncthreads();
    float r = (lane < NW) ? red[lane] : 0.f;
    return warpSum(r);
}
template <int NW>
__device__ __forceinline__ float blockMax(float v, float* red) {
    int w = threadIdx.x >> 5, lane = threadIdx.x & 31;
    v = warpMax(v);
    __syncthreads();
    if (lane == 0) red[w] = v;
    __syncthreads();
    float r = (lane < NW) ? red[lane] : -3.4e38f;
    return warpMax(r);
}

// ---------------- kA0ws: sub (blocks 0..255) + ws row sums (256..383) -------
__global__ __launch_bounds__(256) void kA0ws(
    const float* __restrict__ x, const float* __restrict__ qw,
    const float* __restrict__ ws)
{
    int tid = threadIdx.x, w = tid >> 5, lane = tid & 31;

    if (blockIdx.x >= NH * 4) {
        // ----- ws: scalar[h][o] = sum_i ws[h,o,i]; streams 17MB while kA chain runs
        int wg = (blockIdx.x - NH * 4) * 8 + w;   // 1024 warps, 16 rows each
#pragma unroll 1
        for (int i = 0; i < 16; ++i) {
            int row = wg * 16 + i;                // row = h*256 + o
            const float4* p = (const float4*)(ws + (size_t)row * NOUT);
            float a = 0.f;
#pragma unroll
            for (int j = 0; j < 2; ++j) {
                float4 v = p[j * 32 + lane];
                a += v.x + v.y + v.z + v.w;
            }
            a = warpSum(a);
            if (lane == 0) g_scalar_ho[row] = a;
        }
        return;
    }

    // ----- sub[h][r] = dot(x[r,:], qw[h,:]) -----
    int h = blockIdx.x >> 2, rg = blockIdx.x & 3;
    __shared__ __align__(16) float qws[NINP];
    if (tid < NINP) qws[tid] = qw[h * NINP + tid];
    __syncthreads();

    float4 qv = ((const float4*)qws)[lane];
#pragma unroll
    for (int rr = 0; rr < 4; ++rr) {
        int r = rg * 32 + w * 4 + rr;
        float4 xv = ((const float4*)(x + (size_t)r * NINP))[lane];
        float p = xv.x * qv.x + xv.y * qv.y + xv.z * qv.z + xv.w * qv.w;
        p = warpSum(p);
        if (lane == 0) g_sub[h * NINP + r] = p;
    }
}

// ---------------- kA1: h1pre = w1 @ sub; block = (h, eighth), 64 rows -------
// All 8 rows per warp loaded in flight (8 LDG.128/lane) before reducing.
__global__ __launch_bounds__(256) void kA1(const float* __restrict__ w1)
{
    int h = blockIdx.x >> 3, c = blockIdx.x & 7;
    int tid = threadIdx.x, w = tid >> 5, lane = tid & 31;

    float4 sv = ((const float4*)(g_sub + h * NINP))[lane];

    const float* w1h = w1 + ((size_t)h * NHID + c * 64) * NINP;
    float* dst = g_h1pre + h * NHID + c * 64;
    int r0 = w * 8;

    float4 a[8];
#pragma unroll
    for (int j = 0; j < 8; ++j)
        a[j] = ((const float4*)(w1h + (size_t)(r0 + j) * NINP))[lane];

    float p[8];
#pragma unroll
    for (int j = 0; j < 8; ++j)
        p[j] = a[j].x * sv.x + a[j].y * sv.y + a[j].z * sv.z + a[j].w * sv.w;
#pragma unroll
    for (int j = 0; j < 8; ++j) {
        p[j] = warpSum(p[j]);
        if (lane == 0) dst[r0 + j] = p[j];
    }
}

// ---------------- kA2: GN1+softplus (blocks 0..63) + last_prod (64..71) -----
__global__ __launch_bounds__(512) void kA2(
    const float* __restrict__ g1, const float* __restrict__ b1,
    const float* __restrict__ last)
{
    int tid = threadIdx.x, w = tid >> 5, lane = tid & 31;

    if (blockIdx.x >= NH) {
        int b = blockIdx.x - NH;
#pragma unroll
        for (int i = 0; i < 2; ++i) {
            int o = b * 32 + w * 2 + i;
            float p = last[o * NH + lane] * last[o * NH + 32 + lane];
            p = warpProd(p);
            if (lane == 0) g_lp[o] = p;
        }
        return;
    }

    int h = blockIdx.x;
    __shared__ float red[16];
    float v = g_h1pre[h * NHID + tid];
    float s1 = blockSum<16>(v, red);
    float s2 = blockSum<16>(v * v, red);
    float mu = s1 * (1.f / NHID);
    float var = s2 * (1.f / NHID) - mu * mu;
    float zn = (v - mu) * rsqrtf(var + 1e-5f) * g1[h * NHID + tid] + b1[h * NHID + tid];
    g_h1[h * NHID + tid] = fmaxf(zn, 0.f) + log1pf(expf(-fabsf(zn)));
}

// ---------------- kZ: z = w2·h1; block = (sh, eighth) -> 32 rows, grid 2048 -
__global__ __launch_bounds__(256) void kZ(const float* __restrict__ w2)
{
    int tid = threadIdx.x, w = tid >> 5, lane = tid & 31;
    int sh = blockIdx.x >> 3;       // s*64 + h
    int e  = blockIdx.x & 7;        // eighth of the 256 output rows
    int h  = sh & 63;

    // each warp loads the full 512-float h1 directly (L2-resident, no barrier)
    float4 hv[4];
#pragma unroll
    for (int j = 0; j < 4; ++j)
        hv[j] = ((const float4*)(g_h1 + h * NHID))[j * 32 + lane];

    const float* w2b = w2 + (size_t)sh * NOUT * NHID;
    float* zout = g_z + (size_t)sh * NOUT;
    // 4 rows per warp: 2 iterations with 2 rows (8 LDG.128/lane) in flight
#pragma unroll 1
    for (int rr = 0; rr < 4; rr += 2) {
        int r0 = e * 32 + w * 4 + rr;
        const float4* p0 = (const float4*)(w2b + (size_t)r0 * NHID);
        const float4* p1 = (const float4*)(w2b + (size_t)(r0 + 1) * NHID);
        float a0 = 0.f, a1 = 0.f;
#pragma unroll
        for (int j = 0; j < 4; ++j) {
            float4 u0 = p0[j * 32 + lane];
            float4 u1 = p1[j * 32 + lane];
            a0 += u0.x * hv[j].x + u0.y * hv[j].y + u0.z * hv[j].z + u0.w * hv[j].w;
            a1 += u1.x * hv[j].x + u1.y * hv[j].y + u1.z * hv[j].z + u1.w * hv[j].w;
        }
        a0 = warpSum(a0);
        a1 = warpSum(a1);
        if (lane == 0) { zout[r0] = a0; zout[r0 + 1] = a1; }
    }
}

// ---------------- kP: GN2 + softmax; block per (s,h) ------------------------
__global__ __launch_bounds__(256) void kP(
    const float* __restrict__ g2, const float* __restrict__ b2)
{
    int sh = blockIdx.x, tid = threadIdx.x;
    __shared__ float red[8];

    float z = g_z[(size_t)sh * NOUT + tid];
    float s1 = blockSum<8>(z, red);
    float s2 = blockSum<8>(z * z, red);
    float mu = s1 * (1.f / NOUT);
    float var = s2 * (1.f / NOUT) - mu * mu;
    float zn = (z - mu) * rsqrtf(var + 1e-5f) * g2[sh * NOUT + tid] + b2[sh * NOUT + tid];
    float m = blockMax<8>(zn, red);
    float e = expf(zn - m);
    float se = blockSum<8>(e, red);
    g_partial[sh * NOUT + tid] = e / se;
}

// ---------------- kTail: block per head — out_sm sum, gate, outputs ---------
__global__ __launch_bounds__(256) void kTail(
    const float* __restrict__ woo, float* __restrict__ out)
{
    int h = blockIdx.x, tid = threadIdx.x;
    __shared__ float red[8];

    float osm = 0.f;
#pragma unroll
    for (int s4 = 0; s4 < NSM; ++s4)
        osm += g_partial[(size_t)(s4 * NH + h) * NOUT + tid];

    float term = woo[(size_t)h * 2 * NOUT + tid] * g_lp[tid]
               + woo[(size_t)h * 2 * NOUT + NOUT + tid] * osm;
    float gl = blockSum<8>(term, red);
    float onoff = 1.f / (1.f + expf(-gl));

    float v = onoff * osm;
    out[tid * NH + h] = fmaxf(v, TINYF);
    float v2 = v * g_scalar_ho[h * NOUT + tid];
    out[NOUT * NH + tid * NH + h] = (fabsf(v2) <= TINYF) ? TINYF : v2;
}

// ---------------- launch -----------------------------------------------------
extern "C" void kernel_launch(void* const* d_in, const int* in_sizes, int n_in,
                              void* d_out, int out_size)
{
    const float* x    = (const float*)d_in[0];
    const float* last = (const float*)d_in[1];
    const float* qw   = (const float*)d_in[2];
    const float* w1   = (const float*)d_in[3];
    const float* g1   = (const float*)d_in[4];
    const float* b1   = (const float*)d_in[5];
    const float* w2   = (const float*)d_in[6];
    const float* g2   = (const float*)d_in[7];
    const float* b2   = (const float*)d_in[8];
    const float* ws   = (const float*)d_in[9];
    const float* woo  = (const float*)d_in[10];
    float* out = (float*)d_out;

    kA0ws<<<NH * 4 + 128, 256>>>(x, qw, ws);
    kA1<<<NH * 8, 256>>>(w1);
    kA2<<<NH + 8, 512>>>(g1, b1, last);
    kZ<<<NSM * NH * 8, 256>>>(w2);
    kP<<<NSM * NH, 256>>>(g2, b2);
    kTail<<<NH, 256>>>(woo, out);
}

// round 14
// speedup vs baseline: 1.2963x; 1.2963x over previous
#include <cuda_runtime.h>
#include <math.h>

#define NH   64
#define NINP 128
#define NHID 512
#define NOUT 256
#define NSM  4
#define TINYF 1e-14f

// ---------------- scratch (device globals; no allocations allowed) ----------
__device__ float g_sub[NH * NINP];            // x @ qw_h per head
__device__ float g_h1pre[NH * NHID];          // w1 @ sub, pre-GN
__device__ float g_h1[NH * NHID];             // softplus(GN1(h1pre))
__device__ float g_z[NSM * NH * NOUT];        // w2 @ h1, pre-GN2, [s][h][o]
__device__ float g_partial[NSM * NH * NOUT];  // softmax per (s,h), [s][h][o]
__device__ float g_scalar_ho[NH * NOUT];      // ws row sums, [h][o]
__device__ float g_lp[NOUT];                  // prod over heads of last_out_sm

// ---------------- reduction helpers -----------------------------------------
__device__ __forceinline__ float warpSum(float v) {
#pragma unroll
    for (int o = 16; o; o >>= 1) v += __shfl_xor_sync(0xffffffffu, v, o);
    return v;
}
__device__ __forceinline__ float warpMax(float v) {
#pragma unroll
    for (int o = 16; o; o >>= 1) v = fmaxf(v, __shfl_xor_sync(0xffffffffu, v, o));
    return v;
}
__device__ __forceinline__ float warpProd(float v) {
#pragma unroll
    for (int o = 16; o; o >>= 1) v *= __shfl_xor_sync(0xffffffffu, v, o);
    return v;
}
template <int NW>
__device__ __forceinline__ float blockSum(float v, float* red) {
    int w = threadIdx.x >> 5, lane = threadIdx.x & 31;
    v = warpSum(v);
    __syncthreads();
    if (lane == 0) red[w] = v;
    __syncthreads();
    float r = (lane < NW) ? red[lane] : 0.f;
    return warpSum(r);
}
template <int NW>
__device__ __forceinline__ float blockMax(float v, float* red) {
    int w = threadIdx.x >> 5, lane = threadIdx.x & 31;
    v = warpMax(v);
    __syncthreads();
    if (lane == 0) red[w] = v;
    __syncthreads();
    float r = (lane < NW) ? red[lane] : -3.4e38f;
    return warpMax(r);
}

// ---------------- kA0: sub[h][r] = dot(x[r,:], qw[h,:]); block=(h, rowgroup)
__global__ __launch_bounds__(256) void kA0(
    const float* __restrict__ x, const float* __restrict__ qw)
{
    int h = blockIdx.x >> 2, rg = blockIdx.x & 3;
    __shared__ __align__(16) float qws[NINP];
    int tid = threadIdx.x, w = tid >> 5, lane = tid & 31;

    if (tid < NINP) qws[tid] = qw[h * NINP + tid];
    __syncthreads();

    float4 qv = ((const float4*)qws)[lane];
#pragma unroll
    for (int rr = 0; rr < 4; ++rr) {
        int r = rg * 32 + w * 4 + rr;
        float4 xv = ((const float4*)(x + (size_t)r * NINP))[lane];
        float p = xv.x * qv.x + xv.y * qv.y + xv.z * qv.z + xv.w * qv.w;
        p = warpSum(p);
        if (lane == 0) g_sub[h * NINP + r] = p;
    }
}

// ---------------- kA1: h1pre = w1 @ sub; block = (h, eighth), 64 rows -------
// All 8 rows per warp loaded in flight (8 LDG.128/lane) before reducing.
__global__ __launch_bounds__(256) void kA1(const float* __restrict__ w1)
{
    int h = blockIdx.x >> 3, c = blockIdx.x & 7;
    int tid = threadIdx.x, w = tid >> 5, lane = tid & 31;

    float4 sv = ((const float4*)(g_sub + h * NINP))[lane];

    const float* w1h = w1 + ((size_t)h * NHID + c * 64) * NINP;
    float* dst = g_h1pre + h * NHID + c * 64;
    int r0 = w * 8;

    float4 a[8];
#pragma unroll
    for (int j = 0; j < 8; ++j)
        a[j] = ((const float4*)(w1h + (size_t)(r0 + j) * NINP))[lane];

    float p[8];
#pragma unroll
    for (int j = 0; j < 8; ++j)
        p[j] = a[j].x * sv.x + a[j].y * sv.y + a[j].z * sv.z + a[j].w * sv.w;
#pragma unroll
    for (int j = 0; j < 8; ++j) {
        p[j] = warpSum(p[j]);
        if (lane == 0) dst[r0 + j] = p[j];
    }
}

// ---------------- kA2: GN1+softplus (blocks 0..63) + last_prod (64..71) -----
__global__ __launch_bounds__(512) void kA2(
    const float* __restrict__ g1, const float* __restrict__ b1,
    const float* __restrict__ last)
{
    int tid = threadIdx.x, w = tid >> 5, lane = tid & 31;

    if (blockIdx.x >= NH) {
        int b = blockIdx.x - NH;
#pragma unroll
        for (int i = 0; i < 2; ++i) {
            int o = b * 32 + w * 2 + i;
            float p = last[o * NH + lane] * last[o * NH + 32 + lane];
            p = warpProd(p);
            if (lane == 0) g_lp[o] = p;
        }
        return;
    }

    int h = blockIdx.x;
    __shared__ float red[16];
    float v = g_h1pre[h * NHID + tid];
    float s1 = blockSum<16>(v, red);
    float s2 = blockSum<16>(v * v, red);
    float mu = s1 * (1.f / NHID);
    float var = s2 * (1.f / NHID) - mu * mu;
    float zn = (v - mu) * rsqrtf(var + 1e-5f) * g1[h * NHID + tid] + b1[h * NHID + tid];
    g_h1[h * NHID + tid] = fmaxf(zn, 0.f) + log1pf(expf(-fabsf(zn)));
}

// ---------------- kZws: z = w2·h1 (blocks 0..2047, 32 rows each)
//                  + ws row sums (blocks 2048..2303) — rides the same wave ---
__global__ __launch_bounds__(256) void kZws(
    const float* __restrict__ w2, const float* __restrict__ ws)
{
    int tid = threadIdx.x, w = tid >> 5, lane = tid & 31;

    if (blockIdx.x >= NSM * NH * 8) {
        // ----- ws: scalar[h][o] = sum_i ws[h,o,i]; 2048 warps x 8 rows -----
        int wg = (blockIdx.x - NSM * NH * 8) * 8 + w;
#pragma unroll 1
        for (int i = 0; i < 8; i += 2) {
            int row0 = wg * 8 + i;                 // row = h*256 + o
            const float4* p0 = (const float4*)(ws + (size_t)row0 * NOUT);
            const float4* p1 = (const float4*)(ws + (size_t)(row0 + 1) * NOUT);
            float a0 = 0.f, a1 = 0.f;
#pragma unroll
            for (int j = 0; j < 2; ++j) {
                float4 v0 = p0[j * 32 + lane];
                float4 v1 = p1[j * 32 + lane];
                a0 += v0.x + v0.y + v0.z + v0.w;
                a1 += v1.x + v1.y + v1.z + v1.w;
            }
            a0 = warpSum(a0);
            a1 = warpSum(a1);
            if (lane == 0) { g_scalar_ho[row0] = a0; g_scalar_ho[row0 + 1] = a1; }
        }
        return;
    }

    // ----- z: block = (sh, eighth); 8 warps x 4 rows of 512 -----
    int sh = blockIdx.x >> 3;       // s*64 + h
    int e  = blockIdx.x & 7;        // eighth of the 256 output rows
    int h  = sh & 63;

    // each warp loads the full 512-float h1 directly (L2-resident, no barrier)
    float4 hv[4];
#pragma unroll
    for (int j = 0; j < 4; ++j)
        hv[j] = ((const float4*)(g_h1 + h * NHID))[j * 32 + lane];

    const float* w2b = w2 + (size_t)sh * NOUT * NHID;
    float* zout = g_z + (size_t)sh * NOUT;
#pragma unroll 1
    for (int rr = 0; rr < 4; rr += 2) {
        int r0 = e * 32 + w * 4 + rr;
        const float4* p0 = (const float4*)(w2b + (size_t)r0 * NHID);
        const float4* p1 = (const float4*)(w2b + (size_t)(r0 + 1) * NHID);
        float a0 = 0.f, a1 = 0.f;
#pragma unroll
        for (int j = 0; j < 4; ++j) {
            float4 u0 = p0[j * 32 + lane];
            float4 u1 = p1[j * 32 + lane];
            a0 += u0.x * hv[j].x + u0.y * hv[j].y + u0.z * hv[j].z + u0.w * hv[j].w;
            a1 += u1.x * hv[j].x + u1.y * hv[j].y + u1.z * hv[j].z + u1.w * hv[j].w;
        }
        a0 = warpSum(a0);
        a1 = warpSum(a1);
        if (lane == 0) { zout[r0] = a0; zout[r0 + 1] = a1; }
    }
}

// ---------------- kP: GN2 + softmax; block per (s,h) ------------------------
__global__ __launch_bounds__(256) void kP(
    const float* __restrict__ g2, const float* __restrict__ b2)
{
    int sh = blockIdx.x, tid = threadIdx.x;
    __shared__ float red[8];

    float z = g_z[(size_t)sh * NOUT + tid];
    float s1 = blockSum<8>(z, red);
    float s2 = blockSum<8>(z * z, red);
    float mu = s1 * (1.f / NOUT);
    float var = s2 * (1.f / NOUT) - mu * mu;
    float zn = (z - mu) * rsqrtf(var + 1e-5f) * g2[sh * NOUT + tid] + b2[sh * NOUT + tid];
    float m = blockMax<8>(zn, red);
    float e = expf(zn - m);
    float se = blockSum<8>(e, red);
    g_partial[sh * NOUT + tid] = e / se;
}

// ---------------- kTail: block per head — out_sm sum, gate, outputs ---------
__global__ __launch_bounds__(256) void kTail(
    const float* __restrict__ woo, float* __restrict__ out)
{
    int h = blockIdx.x, tid = threadIdx.x;
    __shared__ float red[8];

    float osm = 0.f;
#pragma unroll
    for (int s4 = 0; s4 < NSM; ++s4)
        osm += g_partial[(size_t)(s4 * NH + h) * NOUT + tid];

    float term = woo[(size_t)h * 2 * NOUT + tid] * g_lp[tid]
               + woo[(size_t)h * 2 * NOUT + NOUT + tid] * osm;
    float gl = blockSum<8>(term, red);
    float onoff = 1.f / (1.f + expf(-gl));

    float v = onoff * osm;
    out[tid * NH + h] = fmaxf(v, TINYF);
    float v2 = v * g_scalar_ho[h * NOUT + tid];
    out[NOUT * NH + tid * NH + h] = (fabsf(v2) <= TINYF) ? TINYF : v2;
}

// ---------------- launch -----------------------------------------------------
extern "C" void kernel_launch(void* const* d_in, const int* in_sizes, int n_in,
                              void* d_out, int out_size)
{
    const float* x    = (const float*)d_in[0];
    const float* last = (const float*)d_in[1];
    const float* qw   = (const float*)d_in[2];
    const float* w1   = (const float*)d_in[3];
    const float* g1   = (const float*)d_in[4];
    const float* b1   = (const float*)d_in[5];
    const float* w2   = (const float*)d_in[6];
    const float* g2   = (const float*)d_in[7];
    const float* b2   = (const float*)d_in[8];
    const float* ws   = (const float*)d_in[9];
    const float* woo  = (const float*)d_in[10];
    float* out = (float*)d_out;

    kA0<<<NH * 4, 256>>>(x, qw);
    kA1<<<NH * 8, 256>>>(w1);
    kA2<<<NH + 8, 512>>>(g1, b1, last);
    kZws<<<NSM * NH * 8 + 256, 256>>>(w2, ws);
    kP<<<NSM * NH, 256>>>(g2, b2);
    kTail<<<NH, 256>>>(woo, out);
}